// round 13
// baseline (speedup 1.0000x reference)
#include <cuda_runtime.h>
#include <cuda_fp16.h>

#define FEAT 4096
#define TT   2048
#define ODIM 512
#define NCTA 148
#define NTHREADS 1024
// SMEM: 16 weight rows (compact) + 4 readout rows, all fp16
#define SMEM_WROWS 16
#define SMEM_OROWS 4
#define SMEMB ((SMEM_WROWS + SMEM_OROWS) * FEAT * 2)   // 163840 B

// Static device scratch (no runtime allocation allowed)
__device__ __half   d_Wh[(size_t)FEAT * FEAT];      // fp16 W_res, 33.5 MB
__device__ __half   d_WoH[(size_t)ODIM * FEAT];     // fp16 w_out, 4 MB
__device__ __half   d_G[(size_t)(TT + 1) * FEAT];   // feats history (fp16)
__device__ float    d_xT[(size_t)TT * FEAT];        // transposed x, 32 MB
__device__ unsigned d_cnt[TT];                      // per-step arrival counters

// ---------------------------------------------------------------------------
// fp32 -> fp16 conversions
// ---------------------------------------------------------------------------
__global__ void convert_kernel(const float* __restrict__ W) {
    size_t n = (size_t)FEAT * FEAT / 4;
    for (size_t i = blockIdx.x * (size_t)blockDim.x + threadIdx.x; i < n;
         i += (size_t)gridDim.x * blockDim.x) {
        float4 v = reinterpret_cast<const float4*>(W)[i];
        __half2 h0 = __floats2half2_rn(v.x, v.y);
        __half2 h1 = __floats2half2_rn(v.z, v.w);
        uint2 u;
        u.x = *reinterpret_cast<unsigned*>(&h0);
        u.y = *reinterpret_cast<unsigned*>(&h1);
        reinterpret_cast<uint2*>(d_Wh)[i] = u;
    }
}

__global__ void convert_wout_kernel(const float* __restrict__ Wo) {
    size_t n = (size_t)ODIM * FEAT / 4;
    for (size_t i = blockIdx.x * (size_t)blockDim.x + threadIdx.x; i < n;
         i += (size_t)gridDim.x * blockDim.x) {
        float4 v = reinterpret_cast<const float4*>(Wo)[i];
        __half2 h0 = __floats2half2_rn(v.x, v.y);
        __half2 h1 = __floats2half2_rn(v.z, v.w);
        uint2 u;
        u.x = *reinterpret_cast<unsigned*>(&h0);
        u.y = *reinterpret_cast<unsigned*>(&h1);
        reinterpret_cast<uint2*>(d_WoH)[i] = u;
    }
}

// ---------------------------------------------------------------------------
// x transpose: x[f][t] -> xT[t][f]  (32x32 tiles)
// ---------------------------------------------------------------------------
__global__ void xpose_kernel(const float* __restrict__ x) {
    __shared__ float tile[32][33];
    int t0 = blockIdx.x * 32;
    int f0 = blockIdx.y * 32;
    int tx = threadIdx.x, ty = threadIdx.y;  // 32 x 8
    #pragma unroll
    for (int r = 0; r < 32; r += 8)
        tile[ty + r][tx] = x[(size_t)(f0 + ty + r) * TT + t0 + tx];
    __syncthreads();
    #pragma unroll
    for (int r = 0; r < 32; r += 8)
        d_xT[(size_t)(t0 + ty + r) * FEAT + f0 + tx] = tile[tx][ty + r];
}

// ---------------------------------------------------------------------------
// Sync primitives (proven: single counter, release-red + tid0 acquire-poll)
// ---------------------------------------------------------------------------
__device__ __forceinline__ unsigned ld_acq(const unsigned* p) {
    unsigned v;
    asm volatile("ld.acquire.gpu.global.u32 %0, [%1];" : "=r"(v) : "l"(p) : "memory");
    return v;
}
__device__ __forceinline__ void red_rel_add1(unsigned* p) {
    asm volatile("red.release.gpu.global.add.u32 [%0], 1;" :: "l"(p) : "memory");
}

__device__ __forceinline__ float dot16(const __half2* wh, const __half2* fh) {
    __half2 a0 = __hmul2(wh[0], fh[0]);
    __half2 a1 = __hmul2(wh[1], fh[1]);
    a0 = __hfma2(wh[2], fh[2], a0);
    a1 = __hfma2(wh[3], fh[3], a1);
    a0 = __hfma2(wh[4], fh[4], a0);
    a1 = __hfma2(wh[5], fh[5], a1);
    a0 = __hfma2(wh[6], fh[6], a0);
    a1 = __hfma2(wh[7], fh[7], a1);
    __half2 s2 = __hadd2(a0, a1);
    return __low2float(s2) + __high2float(s2);
}

// ---------------------------------------------------------------------------
// Persistent recurrence kernel WITH FUSED READOUT.
// 148 CTAs, each owns <=28 W rows + 3..4 w_out rows.
// Recurrence: 3 reg rows + 4 compact-SMEM rows per warp (as R12).
// Readout: out[:, t-1] = w_out @ G[t] computed from the already-loaded fh,
// reduced through sPartOut, finalized by warp 1 in parallel with warp 0's
// recurrence finalize. Fills the sync-wait window; epilogue GEMM eliminated.
// ---------------------------------------------------------------------------
extern "C" __global__ void __launch_bounds__(NTHREADS, 1)
rc_kernel(float* __restrict__ out) {
    extern __shared__ __half smem_[];
    __half* sW  = smem_;                        // [16][FEAT] recurrence rows
    __half* sWo = smem_ + SMEM_WROWS * FEAT;    // [4][FEAT] readout rows
    __shared__ float sPart[2][28][9];           // recurrence partials
    __shared__ float sPartOut[4][9];            // readout partials

    const int b   = blockIdx.x;
    const int tid = threadIdx.x;

    // W-row distribution: first 100 CTAs get 28 rows, last 48 get 27 (=4096).
    int r0, nrows;
    if (b < 100) { r0 = b * 28;                nrows = 28; }
    else         { r0 = 2800 + (b - 100) * 27; nrows = 27; }
    // out-row distribution: first 68 CTAs get 4, last 80 get 3 (=512).
    int o0, nout;
    if (b < 68) { o0 = b * 4;               nout = 4; }
    else        { o0 = 272 + (b - 68) * 3;  nout = 3; }

    // Stage compact W rows: smem row s (0..15) <- CTA row (s/4)*7 + 3 + s%4
    {
        const int VPR = FEAT / 8;               // uint4 per row = 512
        uint4* ws = reinterpret_cast<uint4*>(sW);
        for (int i = tid; i < SMEM_WROWS * VPR; i += NTHREADS) {
            int s   = i / VPR;
            int off = i - s * VPR;
            int ctarow = (s / 4) * 7 + 3 + (s % 4);
            uint4 v = make_uint4(0, 0, 0, 0);
            if (ctarow < nrows)
                v = reinterpret_cast<const uint4*>(
                        d_Wh + (size_t)(r0 + ctarow) * FEAT)[off];
            ws[(size_t)s * VPR + off] = v;
        }
        // Stage w_out rows
        uint4* wo = reinterpret_cast<uint4*>(sWo);
        for (int i = tid; i < SMEM_OROWS * VPR; i += NTHREADS) {
            int s   = i / VPR;
            int off = i - s * VPR;
            uint4 v = make_uint4(0, 0, 0, 0);
            if (s < nout)
                v = reinterpret_cast<const uint4*>(
                        d_WoH + (size_t)(o0 + s) * FEAT)[off];
            wo[(size_t)s * VPR + off] = v;
        }
    }

    const int w    = tid >> 5;
    const int lane = tid & 31;
    const int rg   = w & 3;
    const int kg   = w >> 2;
    const int rbeg = rg * 7;
    const int rend = min(rbeg + 7, nrows);
    const int cb   = kg * 512 + lane * 8;

    // Register-resident weights: this warp's first THREE rows
    __half2 wreg[3][8];
    #pragma unroll
    for (int j = 0; j < 3; ++j) {
        const __half* wr = d_Wh + (size_t)(r0 + rbeg + j) * FEAT + cb;
        uint4 wa = __ldg(reinterpret_cast<const uint4*>(wr));
        uint4 wb = __ldg(reinterpret_cast<const uint4*>(wr + 256));
        __half2* pa = reinterpret_cast<__half2*>(&wa);
        __half2* pb = reinterpret_cast<__half2*>(&wb);
        #pragma unroll
        for (int q = 0; q < 4; ++q) { wreg[j][q] = pa[q]; wreg[j][4 + q] = pb[q]; }
    }
    __syncthreads();

    for (int t = 0; t <= TT; ++t) {
        const bool do_rec = (t < TT);
        // Coalesced x prefetch (in flight during the poll)
        float xv = 0.f;
        if (do_rec && tid < nrows) xv = __ldg(&d_xT[(size_t)t * FEAT + r0 + tid]);

        if (t > 0) {
            if (tid == 0) {
                while (ld_acq(&d_cnt[t - 1]) < NCTA) { }
            }
            __syncthreads();                  // sync1: step-t data visible
        }

        // Features via L1-cacheable loads (4x intra-CTA dedup in L1)
        const __half* f = d_G + (size_t)t * FEAT;
        uint4 fa = __ldg(reinterpret_cast<const uint4*>(f + cb));
        uint4 fb = __ldg(reinterpret_cast<const uint4*>(f + cb + 256));
        __half2 fh[8];
        {
            __half2* pa = reinterpret_cast<__half2*>(&fa);
            __half2* pb = reinterpret_cast<__half2*>(&fb);
            #pragma unroll
            for (int q = 0; q < 4; ++q) { fh[q] = pa[q]; fh[4 + q] = pb[q]; }
        }

        const int par = t & 1;

        if (do_rec) {
            float acc[7];
            #pragma unroll
            for (int j = 0; j < 3; ++j) acc[j] = dot16(wreg[j], fh);
            #pragma unroll
            for (int j = 3; j < 7; ++j) {
                acc[j] = 0.f;
                if (rbeg + j < rend) {
                    const __half* wr = sW + (size_t)(rg * 4 + j - 3) * FEAT + cb;
                    uint4 wa = *reinterpret_cast<const uint4*>(wr);
                    uint4 wb = *reinterpret_cast<const uint4*>(wr + 256);
                    __half2 wh[8];
                    {
                        __half2* pa = reinterpret_cast<__half2*>(&wa);
                        __half2* pb = reinterpret_cast<__half2*>(&wb);
                        #pragma unroll
                        for (int q = 0; q < 4; ++q) { wh[q] = pa[q]; wh[4 + q] = pb[q]; }
                    }
                    acc[j] = dot16(wh, fh);
                }
            }
            #pragma unroll
            for (int j = 0; j < 7; ++j) {
                float v = acc[j];
                v += __shfl_down_sync(0xFFFFFFFFu, v, 16);
                v += __shfl_down_sync(0xFFFFFFFFu, v, 8);
                v += __shfl_down_sync(0xFFFFFFFFu, v, 4);
                v += __shfl_down_sync(0xFFFFFFFFu, v, 2);
                v += __shfl_down_sync(0xFFFFFFFFu, v, 1);
                if (lane == 0 && rbeg + j < rend) sPart[par][rbeg + j][kg] = v;
            }
        }

        // Fused readout partial for column t-1 (uses fh = G[t] = feats_{t-1})
        if (t > 0 && rg < nout) {
            const __half* wr = sWo + (size_t)rg * FEAT + cb;
            uint4 wa = *reinterpret_cast<const uint4*>(wr);
            uint4 wb = *reinterpret_cast<const uint4*>(wr + 256);
            __half2 wh[8];
            {
                __half2* pa = reinterpret_cast<__half2*>(&wa);
                __half2* pb = reinterpret_cast<__half2*>(&wb);
                #pragma unroll
                for (int q = 0; q < 4; ++q) { wh[q] = pa[q]; wh[4 + q] = pb[q]; }
            }
            float v = dot16(wh, fh);
            v += __shfl_down_sync(0xFFFFFFFFu, v, 16);
            v += __shfl_down_sync(0xFFFFFFFFu, v, 8);
            v += __shfl_down_sync(0xFFFFFFFFu, v, 4);
            v += __shfl_down_sync(0xFFFFFFFFu, v, 2);
            v += __shfl_down_sync(0xFFFFFFFFu, v, 1);
            if (lane == 0) sPartOut[rg][kg] = v;
        }
        __syncthreads();                      // sync2: all partials complete

        // Warp 0: recurrence finalize + release (critical path)
        if (do_rec && w == 0) {
            if (lane < nrows) {
                float s = 0.f;
                #pragma unroll
                for (int k = 0; k < 8; ++k) s += sPart[par][lane][k];
                s += xv;
                s = fminf(fmaxf(s, -1.f), 1.f);
                d_G[(size_t)(t + 1) * FEAT + r0 + lane] = __float2half_rn(s);
            }
            __syncwarp();
            if (lane == 0) red_rel_add1(&d_cnt[t]);
        }
        // Warp 1: readout finalize (parallel with warp 0, off critical path)
        if (t > 0 && w == 1) {
            int org = lane >> 3;              // 0..3
            int okg = lane & 7;               // 0..7
            float v = (org < nout) ? sPartOut[org][okg] : 0.f;
            v += __shfl_down_sync(0xFFFFFFFFu, v, 4, 8);
            v += __shfl_down_sync(0xFFFFFFFFu, v, 2, 8);
            v += __shfl_down_sync(0xFFFFFFFFu, v, 1, 8);
            if (okg == 0 && org < nout)
                out[(size_t)(o0 + org) * TT + (t - 1)] = v;
        }
        // sPartOut reuse is safe: no warp passes next sync1 until warp 1
        // (and warp 0) arrive, which happens only after their reads/stores.
    }
}

// ---------------------------------------------------------------------------
extern "C" void kernel_launch(void* const* d_in, const int* in_sizes, int n_in,
                              void* d_out, int out_size) {
    const float* x    = (const float*)d_in[0];   // [4096, 2048]
    const float* Wres = (const float*)d_in[1];   // [4096, 4096]
    const float* wout = (const float*)d_in[2];   // [512, 4096]
    float* out = (float*)d_out;                  // [512, 2048]

    cudaFuncSetAttribute(rc_kernel, cudaFuncAttributeMaxDynamicSharedMemorySize, SMEMB);

    void* cntp = nullptr;
    void* gp   = nullptr;
    cudaGetSymbolAddress(&cntp, d_cnt);
    cudaGetSymbolAddress(&gp, d_G);
    cudaMemsetAsync(cntp, 0, TT * sizeof(unsigned));   // reset step counters
    cudaMemsetAsync(gp, 0, FEAT * sizeof(__half));     // feats_0 = 0 (fp16)

    convert_kernel<<<1024, 256>>>(Wres);
    convert_wout_kernel<<<256, 256>>>(wout);
    xpose_kernel<<<dim3(TT / 32, FEAT / 32), dim3(32, 8)>>>(x);
    rc_kernel<<<NCTA, NTHREADS, SMEMB>>>(out);
}

// round 14
// speedup vs baseline: 1.0604x; 1.0604x over previous
#include <cuda_runtime.h>
#include <cuda_fp16.h>

#define FEAT 4096
#define TT   2048
#define ODIM 512
#define NCTA 148
#define NTHREADS 1024
// SMEM: 16 weight rows (rows 3..6 of each row-group), compact layout
#define SMEM_WROWS 16
#define SMEMB (SMEM_WROWS * FEAT * 2)   // 131072 B -> leaves ~97KB L1

// Static device scratch (no runtime allocation allowed)
__device__ __half   d_Wh[(size_t)FEAT * FEAT];      // fp16 W_res, 33.5 MB
__device__ __half   d_G[(size_t)(TT + 1) * FEAT];   // feats history (fp16), 16.8 MB
__device__ float    d_xT[(size_t)TT * FEAT];        // transposed x, 32 MB
__device__ unsigned d_cnt[TT];                      // per-step arrival counters
__device__ float    d_part[4][(size_t)ODIM * TT];   // split-K partials, 16.8 MB

// ---------------------------------------------------------------------------
// fp32 -> fp16 weight conversion
// ---------------------------------------------------------------------------
__global__ void convert_kernel(const float* __restrict__ W) {
    size_t n = (size_t)FEAT * FEAT / 4;
    for (size_t i = blockIdx.x * (size_t)blockDim.x + threadIdx.x; i < n;
         i += (size_t)gridDim.x * blockDim.x) {
        float4 v = reinterpret_cast<const float4*>(W)[i];
        __half2 h0 = __floats2half2_rn(v.x, v.y);
        __half2 h1 = __floats2half2_rn(v.z, v.w);
        uint2 u;
        u.x = *reinterpret_cast<unsigned*>(&h0);
        u.y = *reinterpret_cast<unsigned*>(&h1);
        reinterpret_cast<uint2*>(d_Wh)[i] = u;
    }
}

// ---------------------------------------------------------------------------
// x transpose: x[f][t] -> xT[t][f]  (32x32 tiles)
// ---------------------------------------------------------------------------
__global__ void xpose_kernel(const float* __restrict__ x) {
    __shared__ float tile[32][33];
    int t0 = blockIdx.x * 32;
    int f0 = blockIdx.y * 32;
    int tx = threadIdx.x, ty = threadIdx.y;  // 32 x 8
    #pragma unroll
    for (int r = 0; r < 32; r += 8)
        tile[ty + r][tx] = x[(size_t)(f0 + ty + r) * TT + t0 + tx];
    __syncthreads();
    #pragma unroll
    for (int r = 0; r < 32; r += 8)
        d_xT[(size_t)(t0 + ty + r) * FEAT + f0 + tx] = tile[tx][ty + r];
}

// ---------------------------------------------------------------------------
// Sync primitives (proven: single counter, release-red + tid0 acquire-poll)
// ---------------------------------------------------------------------------
__device__ __forceinline__ unsigned ld_acq(const unsigned* p) {
    unsigned v;
    asm volatile("ld.acquire.gpu.global.u32 %0, [%1];" : "=r"(v) : "l"(p) : "memory");
    return v;
}
__device__ __forceinline__ void red_rel_add1(unsigned* p) {
    asm volatile("red.release.gpu.global.add.u32 [%0], 1;" :: "l"(p) : "memory");
}

__device__ __forceinline__ float dot16(const __half2* wh, const __half2* fh) {
    __half2 a0 = __hmul2(wh[0], fh[0]);
    __half2 a1 = __hmul2(wh[1], fh[1]);
    a0 = __hfma2(wh[2], fh[2], a0);
    a1 = __hfma2(wh[3], fh[3], a1);
    a0 = __hfma2(wh[4], fh[4], a0);
    a1 = __hfma2(wh[5], fh[5], a1);
    a0 = __hfma2(wh[6], fh[6], a0);
    a1 = __hfma2(wh[7], fh[7], a1);
    __half2 s2 = __hadd2(a0, a1);
    return __low2float(s2) + __high2float(s2);
}

// ---------------------------------------------------------------------------
// Persistent recurrence kernel (R12 skeleton, unchanged — proven best).
// 148 CTAs, each owns <=28 rows of W.
// Rows rbeg..rbeg+2 of each warp: register-resident (3 rows, 24 regs).
// Rows rbeg+3..rbeg+6: compact SMEM (16 rows, 128KB -> ~97KB L1 left).
// Features: plain __ldg -> L1 dedups the 4x intra-CTA reuse without barriers.
// Sync: proven single-counter scheme, 2 CTA barriers/step.
// ---------------------------------------------------------------------------
extern "C" __global__ void __launch_bounds__(NTHREADS, 1)
rc_kernel() {
    extern __shared__ __half sW[];            // [16][FEAT] compact weight rows
    __shared__ float sPart[2][28][9];         // parity-buffered, stride 9

    const int b   = blockIdx.x;
    const int tid = threadIdx.x;

    int r0, nrows;
    if (b < 100) { r0 = b * 28;                nrows = 28; }
    else         { r0 = 2800 + (b - 100) * 27; nrows = 27; }

    // Stage the 16 non-register rows into compact SMEM:
    // smem row s (0..15) <- CTA row (s/4)*7 + 3 + s%4
    {
        const int VPR = FEAT / 8;             // uint4 per row = 512
        uint4* ws = reinterpret_cast<uint4*>(sW);
        for (int i = tid; i < SMEM_WROWS * VPR; i += NTHREADS) {
            int s   = i / VPR;
            int off = i - s * VPR;
            int ctarow = (s / 4) * 7 + 3 + (s % 4);
            uint4 v = make_uint4(0, 0, 0, 0);
            if (ctarow < nrows)
                v = reinterpret_cast<const uint4*>(
                        d_Wh + (size_t)(r0 + ctarow) * FEAT)[off];
            ws[(size_t)s * VPR + off] = v;
        }
    }

    const int w    = tid >> 5;
    const int lane = tid & 31;
    const int rg   = w & 3;
    const int kg   = w >> 2;
    const int rbeg = rg * 7;
    const int rend = min(rbeg + 7, nrows);
    const int cb   = kg * 512 + lane * 8;

    // Register-resident weights: this warp's first THREE rows
    __half2 wreg[3][8];
    #pragma unroll
    for (int j = 0; j < 3; ++j) {
        const __half* wr = d_Wh + (size_t)(r0 + rbeg + j) * FEAT + cb;
        uint4 wa = __ldg(reinterpret_cast<const uint4*>(wr));
        uint4 wb = __ldg(reinterpret_cast<const uint4*>(wr + 256));
        __half2* pa = reinterpret_cast<__half2*>(&wa);
        __half2* pb = reinterpret_cast<__half2*>(&wb);
        #pragma unroll
        for (int q = 0; q < 4; ++q) { wreg[j][q] = pa[q]; wreg[j][4 + q] = pb[q]; }
    }
    __syncthreads();

    for (int t = 0; t < TT; ++t) {
        float xv = 0.f;
        if (tid < nrows) xv = __ldg(&d_xT[(size_t)t * FEAT + r0 + tid]);

        if (t > 0) {
            if (tid == 0) {
                while (ld_acq(&d_cnt[t - 1]) < NCTA) { }
            }
            __syncthreads();                  // sync1: step-t data visible
        }

        const __half* f = d_G + (size_t)t * FEAT;
        uint4 fa = __ldg(reinterpret_cast<const uint4*>(f + cb));
        uint4 fb = __ldg(reinterpret_cast<const uint4*>(f + cb + 256));
        __half2 fh[8];
        {
            __half2* pa = reinterpret_cast<__half2*>(&fa);
            __half2* pb = reinterpret_cast<__half2*>(&fb);
            #pragma unroll
            for (int q = 0; q < 4; ++q) { fh[q] = pa[q]; fh[4 + q] = pb[q]; }
        }

        float acc[7];
        #pragma unroll
        for (int j = 0; j < 3; ++j) acc[j] = dot16(wreg[j], fh);
        #pragma unroll
        for (int j = 3; j < 7; ++j) {
            acc[j] = 0.f;
            if (rbeg + j < rend) {
                const __half* wr = sW + (size_t)(rg * 4 + j - 3) * FEAT + cb;
                uint4 wa = *reinterpret_cast<const uint4*>(wr);
                uint4 wb = *reinterpret_cast<const uint4*>(wr + 256);
                __half2 wh[8];
                {
                    __half2* pa = reinterpret_cast<__half2*>(&wa);
                    __half2* pb = reinterpret_cast<__half2*>(&wb);
                    #pragma unroll
                    for (int q = 0; q < 4; ++q) { wh[q] = pa[q]; wh[4 + q] = pb[q]; }
                }
                acc[j] = dot16(wh, fh);
            }
        }

        const int par = t & 1;
        #pragma unroll
        for (int j = 0; j < 7; ++j) {
            float v = acc[j];
            v += __shfl_down_sync(0xFFFFFFFFu, v, 16);
            v += __shfl_down_sync(0xFFFFFFFFu, v, 8);
            v += __shfl_down_sync(0xFFFFFFFFu, v, 4);
            v += __shfl_down_sync(0xFFFFFFFFu, v, 2);
            v += __shfl_down_sync(0xFFFFFFFFu, v, 1);
            if (lane == 0 && rbeg + j < rend) sPart[par][rbeg + j][kg] = v;
        }
        __syncthreads();                      // sync2: partials complete

        if (w == 0) {
            if (lane < nrows) {
                float s = 0.f;
                #pragma unroll
                for (int k = 0; k < 8; ++k) s += sPart[par][lane][k];
                s += xv;
                s = fminf(fmaxf(s, -1.f), 1.f);
                d_G[(size_t)(t + 1) * FEAT + r0 + lane] = __float2half_rn(s);
            }
            __syncwarp();
            if (lane == 0) red_rel_add1(&d_cnt[t]);
        }
    }
}

// ---------------------------------------------------------------------------
// Readout GEMM v2: 128x128 tile, BK=16, 256 threads, 8x8 micro-tile
// (4 FMA per LDS word vs 2 before -> halves L1 traffic, which was 91% busy).
// Split-K x4 into deterministic partial buffers + reduce.
// ---------------------------------------------------------------------------
__global__ void __launch_bounds__(256)
out_gemm_k(const float* __restrict__ wout) {
    __shared__ float As[16][132];   // As[k][o_local]
    __shared__ float Bs[16][132];   // Bs[k][t_local]

    const int t0 = blockIdx.x * 128;
    const int o0 = blockIdx.y * 128;
    const int kz = blockIdx.z;
    const int tid = threadIdx.x;
    const int tx = tid & 15, ty = tid >> 4;   // 16 x 16 threads

    float c[8][8];
    #pragma unroll
    for (int p = 0; p < 8; ++p)
        #pragma unroll
        for (int q = 0; q < 8; ++q) c[p][q] = 0.f;

    const int kbeg = kz * (FEAT / 4);
    const int kend = kbeg + FEAT / 4;

    for (int k0 = kbeg; k0 < kend; k0 += 16) {
        // A tile: 128 o-rows x 16 k  (2048 floats = 512 float4; 2 per thread)
        #pragma unroll
        for (int it = 0; it < 2; ++it) {
            int idx = it * 256 + tid;          // 0..511
            int i  = idx >> 2;                 // o_local 0..127
            int kv = (idx & 3) * 4;            // 0,4,8,12
            float4 v = *reinterpret_cast<const float4*>(
                &wout[(size_t)(o0 + i) * FEAT + k0 + kv]);
            As[kv + 0][i] = v.x; As[kv + 1][i] = v.y;
            As[kv + 2][i] = v.z; As[kv + 3][i] = v.w;
        }
        // B tile: 128 t-cols x 16 k (fp16 G; 8 halves per thread)
        {
            int j  = tid & 127;                // t_local 0..127
            int kv = (tid >> 7) * 8;           // 0 or 8
            uint4 u = *reinterpret_cast<const uint4*>(
                &d_G[(size_t)(t0 + j + 1) * FEAT + k0 + kv]);
            __half2* h = reinterpret_cast<__half2*>(&u);
            #pragma unroll
            for (int q = 0; q < 4; ++q) {
                float2 fv = __half22float2(h[q]);
                Bs[kv + q * 2 + 0][j] = fv.x;
                Bs[kv + q * 2 + 1][j] = fv.y;
            }
        }
        __syncthreads();

        #pragma unroll
        for (int kk = 0; kk < 16; ++kk) {
            float a[8], bb[8];
            #pragma unroll
            for (int p = 0; p < 8; ++p) a[p] = As[kk][ty * 8 + p];
            #pragma unroll
            for (int q = 0; q < 8; ++q) bb[q] = Bs[kk][tx * 8 + q];
            #pragma unroll
            for (int p = 0; p < 8; ++p)
                #pragma unroll
                for (int q = 0; q < 8; ++q)
                    c[p][q] = fmaf(a[p], bb[q], c[p][q]);
        }
        __syncthreads();
    }

    float* dst = d_part[kz];
    #pragma unroll
    for (int p = 0; p < 8; ++p) {
        float* row = dst + (size_t)(o0 + ty * 8 + p) * TT + t0 + tx * 8;
        #pragma unroll
        for (int q = 0; q < 8; q += 4) {
            float4 v = make_float4(c[p][q], c[p][q + 1], c[p][q + 2], c[p][q + 3]);
            *reinterpret_cast<float4*>(row + q) = v;
        }
    }
}

__global__ void __launch_bounds__(256)
out_reduce(float* __restrict__ out) {
    size_t n = (size_t)ODIM * TT / 4;
    for (size_t i = blockIdx.x * (size_t)blockDim.x + threadIdx.x; i < n;
         i += (size_t)gridDim.x * blockDim.x) {
        float4 a = reinterpret_cast<const float4*>(d_part[0])[i];
        float4 b = reinterpret_cast<const float4*>(d_part[1])[i];
        float4 c = reinterpret_cast<const float4*>(d_part[2])[i];
        float4 d = reinterpret_cast<const float4*>(d_part[3])[i];
        float4 r;
        r.x = (a.x + b.x) + (c.x + d.x);
        r.y = (a.y + b.y) + (c.y + d.y);
        r.z = (a.z + b.z) + (c.z + d.z);
        r.w = (a.w + b.w) + (c.w + d.w);
        reinterpret_cast<float4*>(out)[i] = r;
    }
}

// ---------------------------------------------------------------------------
extern "C" void kernel_launch(void* const* d_in, const int* in_sizes, int n_in,
                              void* d_out, int out_size) {
    const float* x    = (const float*)d_in[0];   // [4096, 2048]
    const float* Wres = (const float*)d_in[1];   // [4096, 4096]
    const float* wout = (const float*)d_in[2];   // [512, 4096]
    float* out = (float*)d_out;                  // [512, 2048]

    cudaFuncSetAttribute(rc_kernel, cudaFuncAttributeMaxDynamicSharedMemorySize, SMEMB);

    void* cntp = nullptr;
    void* gp   = nullptr;
    cudaGetSymbolAddress(&cntp, d_cnt);
    cudaGetSymbolAddress(&gp, d_G);
    cudaMemsetAsync(cntp, 0, TT * sizeof(unsigned));   // reset step counters
    cudaMemsetAsync(gp, 0, FEAT * sizeof(__half));     // feats_0 = 0 (fp16)

    convert_kernel<<<1024, 256>>>(Wres);
    xpose_kernel<<<dim3(TT / 32, FEAT / 32), dim3(32, 8)>>>(x);
    rc_kernel<<<NCTA, NTHREADS, SMEMB>>>();
    out_gemm_k<<<dim3(TT / 128, ODIM / 128, 4), 256>>>(wout);
    out_reduce<<<512, 256>>>(out);
}